// round 8
// baseline (speedup 1.0000x reference)
#include <cuda_runtime.h>
#include <math.h>

// Problem constants
#define SS     5
#define BB     32
#define TT     25
#define TSTEP  24          // T-1 recurrence steps
#define VV     32000
#define EE     512
#define HH     1024
#define GG     3072        // 3*H
#define NROWS  (SS*TSTEP*BB)   // 3840
#define KSPL   4           // K split for step GEMMs (K=1024 -> chunks of 256)

// ---------------- scratch (static device globals; no allocation) ----------------
__device__ float d_x_all[(size_t)NROWS * EE];        // gathered embeddings      7.9 MB
__device__ float d_gi0  [(size_t)NROWS * GG];        // precomputed layer0 gi   47.2 MB
__device__ float d_hs0  [(size_t)SS*TSTEP*BB*HH];    // layer0 hidden per step  15.7 MB
__device__ float d_hs1  [(size_t)SS*TSTEP*BB*HH];    // layer1 hidden per step  15.7 MB
__device__ float d_hc0  [BB*HH];                     // carry state layer0
__device__ float d_hc1  [BB*HH];                     // carry state layer1
__device__ float d_p0   [(size_t)KSPL*GG*BB];        // gh0 K-split partials
__device__ float d_p1i  [(size_t)KSPL*GG*BB];        // gi1 partials
__device__ float d_p1h  [(size_t)KSPL*GG*BB];        // gh1 partials

// ---------------- init: zero carry state every call (deterministic) -------------
__global__ void k_zero_carry() {
    int e = blockIdx.x * blockDim.x + threadIdx.x;
    if (e < BB*HH) { d_hc0[e] = 0.0f; d_hc1[e] = 0.0f; }
}

// ---------------- embedding gather: x_all[r=(s*24+t)*32+b][:] = embed[tok] -----
__global__ void k_gather(const int* __restrict__ ids, const float* __restrict__ embed) {
    int gid = blockIdx.x * blockDim.x + threadIdx.x;
    const int total = NROWS * (EE/4);
    if (gid >= total) return;
    int r   = gid / (EE/4);
    int c   = gid % (EE/4);
    int s   = r / (TSTEP*BB);
    int rem = r % (TSTEP*BB);
    int t   = rem / BB;
    int b   = rem % BB;
    int tok = ids[(s*BB + b)*TT + t];
    reinterpret_cast<float4*>(d_x_all + (size_t)r*EE)[c] =
        reinterpret_cast<const float4*>(embed + (size_t)tok*EE)[c];
}

// ---------------- big tiled SGEMM (NT): C[m,n] = sum_k A[m,k]*B[n,k] -----------
// mode 0: A=d_x_all (K=512), C=d_gi0 (+bias)        -> gi0 precompute
// mode 1: A=d_hs1  (K=1024), C=Cout with (s,t,b)->(s,b,t) remap -> logits
// BM=BN=128, BK=16, 256 threads, 8x8 per thread, register-prefetch double stage.
__global__ __launch_bounds__(256)
void k_sgemm(const float* __restrict__ Bmat, const float* __restrict__ bias,
             float* __restrict__ Cout, int N, int K, int mode)
{
    __shared__ float As[16][128];
    __shared__ float Bs[16][128];

    const float* A = (mode == 0) ? d_x_all : d_hs1;
    int tid = threadIdx.x;
    int m0  = blockIdx.y * 128;
    int n0  = blockIdx.x * 128;

    int lr  = tid >> 1;            // 0..127 : row within tile this thread loads
    int lq0 = (tid & 1) * 2;       // first float4 index (0 or 2) within 16-float chunk

    const float* Ap = A    + (size_t)(m0 + lr) * K;
    const float* Bp = Bmat + (size_t)(n0 + lr) * K;

    float4 av[2], bv[2];
    av[0] = *(const float4*)(Ap + (lq0+0)*4);
    av[1] = *(const float4*)(Ap + (lq0+1)*4);
    bv[0] = *(const float4*)(Bp + (lq0+0)*4);
    bv[1] = *(const float4*)(Bp + (lq0+1)*4);

    float acc[8][8];
#pragma unroll
    for (int i = 0; i < 8; i++)
#pragma unroll
        for (int j = 0; j < 8; j++) acc[i][j] = 0.0f;

    int tx = tid & 15, ty = tid >> 4;

    for (int k0 = 0; k0 < K; k0 += 16) {
#pragma unroll
        for (int u = 0; u < 2; u++) {
            int kq = lq0 + u;
            As[kq*4+0][lr] = av[u].x; As[kq*4+1][lr] = av[u].y;
            As[kq*4+2][lr] = av[u].z; As[kq*4+3][lr] = av[u].w;
            Bs[kq*4+0][lr] = bv[u].x; Bs[kq*4+1][lr] = bv[u].y;
            Bs[kq*4+2][lr] = bv[u].z; Bs[kq*4+3][lr] = bv[u].w;
        }
        __syncthreads();

        int kn = k0 + 16;
        if (kn < K) {   // prefetch next K-block while computing this one
            av[0] = *(const float4*)(Ap + kn + (lq0+0)*4);
            av[1] = *(const float4*)(Ap + kn + (lq0+1)*4);
            bv[0] = *(const float4*)(Bp + kn + (lq0+0)*4);
            bv[1] = *(const float4*)(Bp + kn + (lq0+1)*4);
        }

#pragma unroll
        for (int kk = 0; kk < 16; kk++) {
            float a[8], b[8];
            *(float4*)(a)     = *(const float4*)(&As[kk][ty*8]);
            *(float4*)(a + 4) = *(const float4*)(&As[kk][ty*8 + 4]);
            *(float4*)(b)     = *(const float4*)(&Bs[kk][tx*8]);
            *(float4*)(b + 4) = *(const float4*)(&Bs[kk][tx*8 + 4]);
#pragma unroll
            for (int i = 0; i < 8; i++)
#pragma unroll
                for (int j = 0; j < 8; j++)
                    acc[i][j] += a[i] * b[j];
        }
        __syncthreads();
    }

    if (mode == 0) {
#pragma unroll
        for (int i = 0; i < 8; i++) {
            int m = m0 + ty*8 + i;
            float* crow = d_gi0 + (size_t)m * N + n0 + tx*8;
#pragma unroll
            for (int j = 0; j < 8; j++)
                crow[j] = acc[i][j] + bias[n0 + tx*8 + j];
        }
    } else {
#pragma unroll
        for (int i = 0; i < 8; i++) {
            int m   = m0 + ty*8 + i;
            int s   = m / (TSTEP*BB);
            int rem = m % (TSTEP*BB);
            int t   = rem / BB;
            int b   = rem % BB;
            float* crow = Cout + (((size_t)(s*BB + b)*TSTEP + t) * VV) + n0 + tx*8;
#pragma unroll
            for (int j = 0; j < 8; j++)
                crow[j] = acc[i][j];
        }
    }
}

// ---------------- per-step gate GEMM (K-split partials, deterministic) ---------
// out[(ks*GG + j)*BB + b] = sum_{k in chunk ks} W[j,k] * x[b,k]
// layer==0           : W=Wa (W_hh0), x = hprev0,        out=d_p0
// layer==1, z==0     : W=Wa (W_ih1), x = h0n (this t),  out=d_p1i
// layer==1, z==1     : W=Wb (W_hh1), x = hprev1,        out=d_p1h
// CTA: 64j x 32b tile, 128 threads, 4x4 per thread. K always HH.
__global__ __launch_bounds__(128)
void k_step_gemm(const float* __restrict__ Wa, const float* __restrict__ Wb,
                 int layer, int s, int t)
{
    __shared__ float Ws[16][64];
    __shared__ float Xs[16][32];

    const float* W;
    const float* x;
    float* out;
    if (layer == 0) {
        W = Wa;
        x = (t == 0) ? d_hc0 : (d_hs0 + (size_t)(s*TSTEP + t - 1) * BB * HH);
        out = d_p0;
    } else if (blockIdx.z == 0) {
        W = Wa;
        x = d_hs0 + (size_t)(s*TSTEP + t) * BB * HH;
        out = d_p1i;
    } else {
        W = Wb;
        x = (t == 0) ? d_hc1 : (d_hs1 + (size_t)(s*TSTEP + t - 1) * BB * HH);
        out = d_p1h;
    }

    int tid = threadIdx.x;
    int j0  = blockIdx.x * 64;
    int ks  = blockIdx.y;
    const int kchunk = HH / KSPL;   // 256
    int kbeg = ks * kchunk;

    float acc[4][4];
#pragma unroll
    for (int i = 0; i < 4; i++)
#pragma unroll
        for (int j = 0; j < 4; j++) acc[i][j] = 0.0f;

    int jg = tid >> 3;   // 0..15
    int bg = tid & 7;    // 0..7
    int wr = tid >> 1;   // 0..63
    int xr = tid >> 2;   // 0..31

    for (int k0 = kbeg; k0 < kbeg + kchunk; k0 += 16) {
#pragma unroll
        for (int u = 0; u < 2; u++) {
            int kq = (tid & 1) * 2 + u;
            float4 wv = *(const float4*)(W + (size_t)(j0 + wr)*HH + k0 + kq*4);
            Ws[kq*4+0][wr] = wv.x; Ws[kq*4+1][wr] = wv.y;
            Ws[kq*4+2][wr] = wv.z; Ws[kq*4+3][wr] = wv.w;
        }
        {
            int kq = tid & 3;
            float4 xv = *(const float4*)(x + (size_t)xr*HH + k0 + kq*4);
            Xs[kq*4+0][xr] = xv.x; Xs[kq*4+1][xr] = xv.y;
            Xs[kq*4+2][xr] = xv.z; Xs[kq*4+3][xr] = xv.w;
        }
        __syncthreads();
#pragma unroll
        for (int kk = 0; kk < 16; kk++) {
            float a[4], b[4];
            *(float4*)a = *(const float4*)(&Ws[kk][jg*4]);
            *(float4*)b = *(const float4*)(&Xs[kk][bg*4]);
#pragma unroll
            for (int i = 0; i < 4; i++)
#pragma unroll
                for (int j = 0; j < 4; j++)
                    acc[i][j] += a[i] * b[j];
        }
        __syncthreads();
    }

#pragma unroll
    for (int i = 0; i < 4; i++) {
        int j = j0 + jg*4 + i;
        float4 v = make_float4(acc[i][0], acc[i][1], acc[i][2], acc[i][3]);
        *(float4*)(out + ((size_t)ks*GG + j) * BB + bg*4) = v;
    }
}

// ---------------- GRU pointwise, layer 0 (reduce partials + gates) -------------
__global__ void k_gru0(const float* __restrict__ bhh, int s, int t)
{
    int e = blockIdx.x * blockDim.x + threadIdx.x;
    if (e >= BB*HH) return;
    int b = e >> 10;
    int i = e & (HH - 1);

    float gr = bhh[i], gz = bhh[HH+i], gn = bhh[2*HH+i];
#pragma unroll
    for (int ks = 0; ks < KSPL; ks++) {
        const float* p = d_p0 + (size_t)ks*GG*BB;
        gr += p[(size_t)(i       )*BB + b];
        gz += p[(size_t)(HH  + i )*BB + b];
        gn += p[(size_t)(2*HH + i)*BB + b];
    }
    const float* gi = d_gi0 + ((size_t)(s*TSTEP + t)*BB + b) * GG;
    float ir = gi[i], iz = gi[HH+i], inn = gi[2*HH+i];

    const float* hp = (t == 0) ? d_hc0 : (d_hs0 + (size_t)(s*TSTEP + t - 1)*BB*HH);
    float hprev = hp[(size_t)b*HH + i];

    float r = 1.0f / (1.0f + expf(-(ir + gr)));
    float z = 1.0f / (1.0f + expf(-(iz + gz)));
    float n = tanhf(inn + r * gn);
    d_hs0[((size_t)(s*TSTEP + t)*BB + b)*HH + i] = (1.0f - z)*n + z*hprev;
}

// ---------------- GRU pointwise, layer 1 ---------------------------------------
__global__ void k_gru1(const float* __restrict__ bih, const float* __restrict__ bhh,
                       int s, int t)
{
    int e = blockIdx.x * blockDim.x + threadIdx.x;
    if (e >= BB*HH) return;
    int b = e >> 10;
    int i = e & (HH - 1);

    float ir = bih[i], iz = bih[HH+i], inn = bih[2*HH+i];
    float gr = bhh[i], gz = bhh[HH+i], gn  = bhh[2*HH+i];
#pragma unroll
    for (int ks = 0; ks < KSPL; ks++) {
        const float* pi = d_p1i + (size_t)ks*GG*BB;
        const float* ph = d_p1h + (size_t)ks*GG*BB;
        ir  += pi[(size_t)(i       )*BB + b];
        iz  += pi[(size_t)(HH  + i )*BB + b];
        inn += pi[(size_t)(2*HH + i)*BB + b];
        gr  += ph[(size_t)(i       )*BB + b];
        gz  += ph[(size_t)(HH  + i )*BB + b];
        gn  += ph[(size_t)(2*HH + i)*BB + b];
    }
    const float* hp = (t == 0) ? d_hc1 : (d_hs1 + (size_t)(s*TSTEP + t - 1)*BB*HH);
    float hprev = hp[(size_t)b*HH + i];

    float r = 1.0f / (1.0f + expf(-(ir + gr)));
    float z = 1.0f / (1.0f + expf(-(iz + gz)));
    float n = tanhf(inn + r * gn);
    d_hs1[((size_t)(s*TSTEP + t)*BB + b)*HH + i] = (1.0f - z)*n + z*hprev;
}

// ---------------- per-sentence carry: h <- hs[clip(len-2,0,23)] ----------------
__global__ void k_carry(const int* __restrict__ lens, int s)
{
    int e = blockIdx.x * blockDim.x + threadIdx.x;
    if (e >= BB*HH) return;
    int b = e >> 10;
    int i = e & (HH - 1);
    int idx = lens[s*BB + b] - 2;
    if (idx < 0) idx = 0;
    if (idx > TSTEP - 1) idx = TSTEP - 1;
    d_hc0[(size_t)b*HH + i] = d_hs0[((size_t)(s*TSTEP + idx)*BB + b)*HH + i];
    d_hc1[(size_t)b*HH + i] = d_hs1[((size_t)(s*TSTEP + idx)*BB + b)*HH + i];
}

// ---------------- launcher ------------------------------------------------------
extern "C" void kernel_launch(void* const* d_in, const int* in_sizes, int n_in,
                              void* d_out, int out_size)
{
    (void)in_sizes; (void)n_in; (void)out_size;
    const int*   ids    = (const int*)  d_in[0];
    const int*   lens   = (const int*)  d_in[1];
    const float* embed  = (const float*)d_in[2];
    const float* W_ih0  = (const float*)d_in[3];
    const float* W_hh0  = (const float*)d_in[4];
    const float* b_ih0  = (const float*)d_in[5];
    const float* b_hh0  = (const float*)d_in[6];
    const float* W_ih1  = (const float*)d_in[7];
    const float* W_hh1  = (const float*)d_in[8];
    const float* b_ih1  = (const float*)d_in[9];
    const float* b_hh1  = (const float*)d_in[10];
    const float* W_out  = (const float*)d_in[11];
    float*       out    = (float*)d_out;

    // reset carry state (graph replays must be deterministic)
    k_zero_carry<<<(BB*HH + 255)/256, 256>>>();

    // gather embeddings for all (s,b,t)
    k_gather<<<(NROWS*(EE/4) + 255)/256, 256>>>(ids, embed);

    // precompute all layer-0 input gates: gi0 = x_all @ W_ih0^T + b_ih0
    k_sgemm<<<dim3(GG/128, NROWS/128), 256>>>(W_ih0, b_ih0, nullptr, GG, EE, 0);

    // sequential recurrence
    for (int s = 0; s < SS; s++) {
        for (int t = 0; t < TSTEP; t++) {
            k_step_gemm<<<dim3(GG/64, KSPL, 1), 128>>>(W_hh0, nullptr, 0, s, t);
            k_gru0<<<(BB*HH)/256, 256>>>(b_hh0, s, t);
            k_step_gemm<<<dim3(GG/64, KSPL, 2), 128>>>(W_ih1, W_hh1, 1, s, t);
            k_gru1<<<(BB*HH)/256, 256>>>(b_ih1, b_hh1, s, t);
        }
        k_carry<<<(BB*HH)/256, 256>>>(lens, s);
    }

    // logits = hs1 @ W_out^T, remapped to (s, b, t, v)
    k_sgemm<<<dim3(VV/128, NROWS/128), 256>>>(W_out, nullptr, out, VV, HH, 1);
}

// round 10
// speedup vs baseline: 1.3650x; 1.3650x over previous
#include <cuda_runtime.h>
#include <cuda_bf16.h>
#include <stdint.h>
#include <math.h>

// Problem constants
#define SS     5
#define BB     32
#define TT     25
#define TSTEP  24          // T-1 recurrence steps
#define VV     32000
#define EE     512
#define HH     1024
#define GG     3072        // 3*H
#define NROWS  (SS*TSTEP*BB)   // 3840
#define KSPL   4           // K split for step GEMMs (K=1024 -> chunks of 256)
#define KP     (HH/2)      // 512 packed uint2 per row (hi-pair, lo-pair)

// ---------------- scratch (static device globals; no allocation) ----------------
__device__ float d_x_all[(size_t)NROWS * EE];        // gathered embeddings
__device__ float d_gi0  [(size_t)NROWS * GG];        // precomputed layer0 gi
__device__ float d_hs0  [(size_t)NROWS * HH];        // layer0 hidden per step (fp32)
__device__ float d_hs1  [(size_t)NROWS * HH];        // layer1 hidden per step (fp32)
__device__ float d_hc0  [BB*HH];                     // carry state layer0 (fp32)
__device__ float d_hc1  [BB*HH];                     // carry state layer1 (fp32)
__device__ float d_p0   [(size_t)KSPL*GG*BB];        // gh0 K-split partials
__device__ float d_p1i  [(size_t)KSPL*GG*BB];        // gi1 partials
__device__ float d_p1h  [(size_t)KSPL*GG*BB];        // gh1 partials

// packed split-bf16 operands: uint2 per 2 k-elems: {x = hi|hi<<16, y = lo|lo<<16}
__device__ uint2 d_Wp0 [(size_t)GG*KP];              // W_hh0 packed  (12.6MB)
__device__ uint2 d_Wp1i[(size_t)GG*KP];              // W_ih1 packed
__device__ uint2 d_Wp1h[(size_t)GG*KP];              // W_hh1 packed
__device__ uint2 d_WpO [(size_t)VV*KP];              // W_out packed  (131MB)
__device__ uint2 d_hs0p[(size_t)NROWS*KP];           // layer0 hidden packed
__device__ uint2 d_hs1p[(size_t)NROWS*KP];           // layer1 hidden packed (logits A)
__device__ uint2 d_hc0p[(size_t)BB*KP];              // carry packed
__device__ uint2 d_hc1p[(size_t)BB*KP];

// ---------------- helpers -------------------------------------------------------
__device__ __forceinline__ uint2 packpair(float x, float y) {
    __nv_bfloat16 hx = __float2bfloat16_rn(x);
    __nv_bfloat16 hy = __float2bfloat16_rn(y);
    float rx = x - __bfloat162float(hx);
    float ry = y - __bfloat162float(hy);
    __nv_bfloat16 lx = __float2bfloat16_rn(rx);
    __nv_bfloat16 ly = __float2bfloat16_rn(ry);
    unsigned short uhx = __bfloat16_as_ushort(hx);
    unsigned short uhy = __bfloat16_as_ushort(hy);
    unsigned short ulx = __bfloat16_as_ushort(lx);
    unsigned short uly = __bfloat16_as_ushort(ly);
    uint2 o;
    o.x = (unsigned int)uhx | ((unsigned int)uhy << 16);
    o.y = (unsigned int)ulx | ((unsigned int)uly << 16);
    return o;
}

__device__ __forceinline__ void mma16816(float& d0, float& d1, float& d2, float& d3,
                                         unsigned int a0, unsigned int a1,
                                         unsigned int a2, unsigned int a3,
                                         unsigned int b0, unsigned int b1) {
    asm volatile(
        "mma.sync.aligned.m16n8k16.row.col.f32.bf16.bf16.f32 "
        "{%0,%1,%2,%3}, {%4,%5,%6,%7}, {%8,%9}, {%0,%1,%2,%3};\n"
        : "+f"(d0), "+f"(d1), "+f"(d2), "+f"(d3)
        : "r"(a0), "r"(a1), "r"(a2), "r"(a3), "r"(b0), "r"(b1));
}

// split-bf16: d += Ahi*Bhi + Ahi*Blo + Alo*Bhi
__device__ __forceinline__ void mma3(float* d, uint2 a0, uint2 a1, uint2 a2, uint2 a3,
                                     uint2 b0, uint2 b1) {
    mma16816(d[0], d[1], d[2], d[3], a0.x, a1.x, a2.x, a3.x, b0.x, b1.x);
    mma16816(d[0], d[1], d[2], d[3], a0.x, a1.x, a2.x, a3.x, b0.y, b1.y);
    mma16816(d[0], d[1], d[2], d[3], a0.y, a1.y, a2.y, a3.y, b0.x, b1.x);
}

// ---------------- weight packing ------------------------------------------------
__global__ void k_packw(const float* __restrict__ src, uint2* __restrict__ dst, int npairs) {
    int i = blockIdx.x * blockDim.x + threadIdx.x;
    if (i >= npairs) return;
    float2 v = reinterpret_cast<const float2*>(src)[i];
    dst[i] = packpair(v.x, v.y);
}

// ---------------- init: zero carry state (fp32 + packed) ------------------------
__global__ void k_zero_carry() {
    int e = blockIdx.x * blockDim.x + threadIdx.x;
    if (e >= BB*HH/2) return;
    reinterpret_cast<float2*>(d_hc0)[e] = make_float2(0.f, 0.f);
    reinterpret_cast<float2*>(d_hc1)[e] = make_float2(0.f, 0.f);
    d_hc0p[e] = make_uint2(0u, 0u);
    d_hc1p[e] = make_uint2(0u, 0u);
}

// ---------------- embedding gather ----------------------------------------------
__global__ void k_gather(const int* __restrict__ ids, const float* __restrict__ embed) {
    int gid = blockIdx.x * blockDim.x + threadIdx.x;
    const int total = NROWS * (EE/4);
    if (gid >= total) return;
    int r   = gid / (EE/4);
    int c   = gid % (EE/4);
    int s   = r / (TSTEP*BB);
    int rem = r % (TSTEP*BB);
    int t   = rem / BB;
    int b   = rem % BB;
    int tok = ids[(s*BB + b)*TT + t];
    reinterpret_cast<float4*>(d_x_all + (size_t)r*EE)[c] =
        reinterpret_cast<const float4*>(embed + (size_t)tok*EE)[c];
}

// ---------------- fp32 SGEMM for gi0 precompute (K=512) -------------------------
__global__ __launch_bounds__(256)
void k_sgemm(const float* __restrict__ Bmat, const float* __restrict__ bias,
             int N, int K)
{
    __shared__ float As[16][128];
    __shared__ float Bs[16][128];

    const float* A = d_x_all;
    int tid = threadIdx.x;
    int m0  = blockIdx.y * 128;
    int n0  = blockIdx.x * 128;

    int lr  = tid >> 1;
    int lq0 = (tid & 1) * 2;

    const float* Ap = A    + (size_t)(m0 + lr) * K;
    const float* Bp = Bmat + (size_t)(n0 + lr) * K;

    float4 av[2], bv[2];
    av[0] = *(const float4*)(Ap + (lq0+0)*4);
    av[1] = *(const float4*)(Ap + (lq0+1)*4);
    bv[0] = *(const float4*)(Bp + (lq0+0)*4);
    bv[1] = *(const float4*)(Bp + (lq0+1)*4);

    float acc[8][8];
#pragma unroll
    for (int i = 0; i < 8; i++)
#pragma unroll
        for (int j = 0; j < 8; j++) acc[i][j] = 0.0f;

    int tx = tid & 15, ty = tid >> 4;

    for (int k0 = 0; k0 < K; k0 += 16) {
#pragma unroll
        for (int u = 0; u < 2; u++) {
            int kq = lq0 + u;
            As[kq*4+0][lr] = av[u].x; As[kq*4+1][lr] = av[u].y;
            As[kq*4+2][lr] = av[u].z; As[kq*4+3][lr] = av[u].w;
            Bs[kq*4+0][lr] = bv[u].x; Bs[kq*4+1][lr] = bv[u].y;
            Bs[kq*4+2][lr] = bv[u].z; Bs[kq*4+3][lr] = bv[u].w;
        }
        __syncthreads();

        int kn = k0 + 16;
        if (kn < K) {
            av[0] = *(const float4*)(Ap + kn + (lq0+0)*4);
            av[1] = *(const float4*)(Ap + kn + (lq0+1)*4);
            bv[0] = *(const float4*)(Bp + kn + (lq0+0)*4);
            bv[1] = *(const float4*)(Bp + kn + (lq0+1)*4);
        }

#pragma unroll
        for (int kk = 0; kk < 16; kk++) {
            float a[8], b[8];
            *(float4*)(a)     = *(const float4*)(&As[kk][ty*8]);
            *(float4*)(a + 4) = *(const float4*)(&As[kk][ty*8 + 4]);
            *(float4*)(b)     = *(const float4*)(&Bs[kk][tx*8]);
            *(float4*)(b + 4) = *(const float4*)(&Bs[kk][tx*8 + 4]);
#pragma unroll
            for (int i = 0; i < 8; i++)
#pragma unroll
                for (int j = 0; j < 8; j++)
                    acc[i][j] += a[i] * b[j];
        }
        __syncthreads();
    }

#pragma unroll
    for (int i = 0; i < 8; i++) {
        int m = m0 + ty*8 + i;
        float* crow = d_gi0 + (size_t)m * N + n0 + tx*8;
#pragma unroll
        for (int j = 0; j < 8; j++)
            crow[j] = acc[i][j] + bias[n0 + tx*8 + j];
    }
}

// ---------------- step GEMM via split-bf16 mma ----------------------------------
// out[(ks*GG + j)*BB + b] = sum_{k in chunk} W[j,k] * x[b,k]
// grid: (48 j-tiles of 64, KSPL, nmat), 128 threads (4 warps, warp=16j x 32b).
__global__ __launch_bounds__(128)
void k_mma_step(const uint2* __restrict__ Wp_a, const uint2* __restrict__ Wp_b,
                int layer, int s, int t)
{
    const uint2* W; const uint2* xp; float* out;
    if (layer == 0) {
        W = Wp_a;
        xp = (t == 0) ? d_hc0p : (d_hs0p + (size_t)(s*TSTEP + t - 1) * BB * KP);
        out = d_p0;
    } else if (blockIdx.z == 0) {
        W = Wp_a;
        xp = d_hs0p + (size_t)(s*TSTEP + t) * BB * KP;
        out = d_p1i;
    } else {
        W = Wp_b;
        xp = (t == 0) ? d_hc1p : (d_hs1p + (size_t)(s*TSTEP + t - 1) * BB * KP);
        out = d_p1h;
    }

    int wid = threadIdx.x >> 5, lane = threadIdx.x & 31;
    int g = lane >> 2, tg = lane & 3;
    int j0 = blockIdx.x * 64 + wid * 16;
    int ks = blockIdx.y;
    int kc0 = ks * (KP / KSPL);        // 128 uint2 per chunk

    float acc[4][4];
#pragma unroll
    for (int q = 0; q < 4; q++)
#pragma unroll
        for (int i = 0; i < 4; i++) acc[q][i] = 0.0f;

    const uint2* Wr0 = W + (size_t)(j0 + g    ) * KP + kc0 + tg;
    const uint2* Wr1 = W + (size_t)(j0 + g + 8) * KP + kc0 + tg;

#pragma unroll 2
    for (int kk = 0; kk < 16; kk++) {          // 16 x k16 = K chunk 256
        int kc = kk * 8;
        uint2 a0 = Wr0[kc];
        uint2 a2 = Wr0[kc + 4];
        uint2 a1 = Wr1[kc];
        uint2 a3 = Wr1[kc + 4];
#pragma unroll
        for (int q = 0; q < 4; q++) {
            const uint2* xr = xp + (size_t)(8*q + g) * KP + kc0 + kc + tg;
            uint2 b0 = xr[0];
            uint2 b1 = xr[4];
            mma3(acc[q], a0, a1, a2, a3, b0, b1);
        }
    }

#pragma unroll
    for (int q = 0; q < 4; q++) {
        int b = 8*q + 2*tg;
        *(float2*)(out + ((size_t)ks*GG + j0 + g    )*BB + b) = make_float2(acc[q][0], acc[q][1]);
        *(float2*)(out + ((size_t)ks*GG + j0 + g + 8)*BB + b) = make_float2(acc[q][2], acc[q][3]);
    }
}

// ---------------- logits GEMM via split-bf16 mma --------------------------------
// C[m=3840, n=32000] = hs1 @ W_out^T ; CTA 128x128, 8 warps (2x4), warp 64x32.
__global__ __launch_bounds__(256)
void k_mma_logits(float* __restrict__ out)
{
    int wid = threadIdx.x >> 5, lane = threadIdx.x & 31;
    int g = lane >> 2, tg = lane & 3;
    int wm = wid >> 2, wn = wid & 3;
    int m0 = blockIdx.x * 128 + wm * 64;
    int n0 = blockIdx.y * 128 + wn * 32;

    float acc[4][4][4];
#pragma unroll
    for (int mi = 0; mi < 4; mi++)
#pragma unroll
        for (int q = 0; q < 4; q++)
#pragma unroll
            for (int i = 0; i < 4; i++) acc[mi][q][i] = 0.0f;

#pragma unroll 2
    for (int kc = 0; kc < KP; kc += 8) {       // k16 steps over K=1024
        uint2 a[4][4];
#pragma unroll
        for (int mi = 0; mi < 4; mi++) {
            const uint2* Ar0 = d_hs1p + (size_t)(m0 + mi*16 + g    ) * KP + kc + tg;
            const uint2* Ar1 = d_hs1p + (size_t)(m0 + mi*16 + g + 8) * KP + kc + tg;
            a[mi][0] = Ar0[0];
            a[mi][2] = Ar0[4];
            a[mi][1] = Ar1[0];
            a[mi][3] = Ar1[4];
        }
#pragma unroll
        for (int q = 0; q < 4; q++) {
            const uint2* Br = d_WpO + (size_t)(n0 + 8*q + g) * KP + kc + tg;
            uint2 b0 = Br[0];
            uint2 b1 = Br[4];
#pragma unroll
            for (int mi = 0; mi < 4; mi++)
                mma3(acc[mi][q], a[mi][0], a[mi][1], a[mi][2], a[mi][3], b0, b1);
        }
    }

    // epilogue with (s,t,b)->(s,b,t) remap
#pragma unroll
    for (int mi = 0; mi < 4; mi++) {
        int mA = m0 + mi*16 + g;
        int mB = mA + 8;
        int sA = mA / (TSTEP*BB); int rA = mA % (TSTEP*BB);
        int sB = mB / (TSTEP*BB); int rB = mB % (TSTEP*BB);
        size_t rowA = ((size_t)(sA*BB + (rA % BB))*TSTEP + (rA / BB)) * VV;
        size_t rowB = ((size_t)(sB*BB + (rB % BB))*TSTEP + (rB / BB)) * VV;
#pragma unroll
        for (int q = 0; q < 4; q++) {
            int col = n0 + 8*q + 2*tg;
            *(float2*)(out + rowA + col) = make_float2(acc[mi][q][0], acc[mi][q][1]);
            *(float2*)(out + rowB + col) = make_float2(acc[mi][q][2], acc[mi][q][3]);
        }
    }
}

// ---------------- GRU pointwise, layer 0 (vectorized x2, emits packed) ----------
__global__ void k_gru0(const float* __restrict__ bhh, int s, int t)
{
    int e = blockIdx.x * blockDim.x + threadIdx.x;
    if (e >= BB*HH/2) return;
    int b  = e >> 9;          // HH/2 = 512 pairs per batch row
    int kc = e & 511;
    int i  = kc * 2;

    float gr0 = bhh[i],      gr1 = bhh[i+1];
    float gz0 = bhh[HH+i],   gz1 = bhh[HH+i+1];
    float gn0 = bhh[2*HH+i], gn1 = bhh[2*HH+i+1];
#pragma unroll
    for (int ks = 0; ks < KSPL; ks++) {
        const float* p = d_p0 + (size_t)ks*GG*BB;
        gr0 += p[(size_t)(i         )*BB + b]; gr1 += p[(size_t)(i+1       )*BB + b];
        gz0 += p[(size_t)(HH + i    )*BB + b]; gz1 += p[(size_t)(HH + i+1  )*BB + b];
        gn0 += p[(size_t)(2*HH + i  )*BB + b]; gn1 += p[(size_t)(2*HH + i+1)*BB + b];
    }
    const float* gi = d_gi0 + ((size_t)(s*TSTEP + t)*BB + b) * GG;
    float2 irv = *(const float2*)(gi + i);
    float2 izv = *(const float2*)(gi + HH + i);
    float2 inv = *(const float2*)(gi + 2*HH + i);

    const float* hp = (t == 0) ? d_hc0 : (d_hs0 + (size_t)(s*TSTEP + t - 1)*BB*HH);
    float2 hpv = *(const float2*)(hp + (size_t)b*HH + i);

    float r0 = 1.0f / (1.0f + expf(-(irv.x + gr0)));
    float r1 = 1.0f / (1.0f + expf(-(irv.y + gr1)));
    float z0 = 1.0f / (1.0f + expf(-(izv.x + gz0)));
    float z1 = 1.0f / (1.0f + expf(-(izv.y + gz1)));
    float n0 = tanhf(inv.x + r0 * gn0);
    float n1 = tanhf(inv.y + r1 * gn1);
    float h0 = (1.0f - z0)*n0 + z0*hpv.x;
    float h1 = (1.0f - z1)*n1 + z1*hpv.y;

    size_t base = ((size_t)(s*TSTEP + t)*BB + b);
    *(float2*)(d_hs0 + base*HH + i) = make_float2(h0, h1);
    d_hs0p[base*KP + kc] = packpair(h0, h1);
}

// ---------------- GRU pointwise, layer 1 ----------------------------------------
__global__ void k_gru1(const float* __restrict__ bih, const float* __restrict__ bhh,
                       int s, int t)
{
    int e = blockIdx.x * blockDim.x + threadIdx.x;
    if (e >= BB*HH/2) return;
    int b  = e >> 9;
    int kc = e & 511;
    int i  = kc * 2;

    float ir0 = bih[i],      ir1 = bih[i+1];
    float iz0 = bih[HH+i],   iz1 = bih[HH+i+1];
    float in0 = bih[2*HH+i], in1 = bih[2*HH+i+1];
    float gr0 = bhh[i],      gr1 = bhh[i+1];
    float gz0 = bhh[HH+i],   gz1 = bhh[HH+i+1];
    float gn0 = bhh[2*HH+i], gn1 = bhh[2*HH+i+1];
#pragma unroll
    for (int ks = 0; ks < KSPL; ks++) {
        const float* pi = d_p1i + (size_t)ks*GG*BB;
        const float* ph = d_p1h + (size_t)ks*GG*BB;
        ir0 += pi[(size_t)(i         )*BB + b]; ir1 += pi[(size_t)(i+1       )*BB + b];
        iz0 += pi[(size_t)(HH + i    )*BB + b]; iz1 += pi[(size_t)(HH + i+1  )*BB + b];
        in0 += pi[(size_t)(2*HH + i  )*BB + b]; in1 += pi[(size_t)(2*HH + i+1)*BB + b];
        gr0 += ph[(size_t)(i         )*BB + b]; gr1 += ph[(size_t)(i+1       )*BB + b];
        gz0 += ph[(size_t)(HH + i    )*BB + b]; gz1 += ph[(size_t)(HH + i+1  )*BB + b];
        gn0 += ph[(size_t)(2*HH + i  )*BB + b]; gn1 += ph[(size_t)(2*HH + i+1)*BB + b];
    }
    const float* hp = (t == 0) ? d_hc1 : (d_hs1 + (size_t)(s*TSTEP + t - 1)*BB*HH);
    float2 hpv = *(const float2*)(hp + (size_t)b*HH + i);

    float r0 = 1.0f / (1.0f + expf(-(ir0 + gr0)));
    float r1 = 1.0f / (1.0f + expf(-(ir1 + gr1)));
    float z0 = 1.0f / (1.0f + expf(-(iz0 + gz0)));
    float z1 = 1.0f / (1.0f + expf(-(iz1 + gz1)));
    float n0 = tanhf(in0 + r0 * gn0);
    float n1 = tanhf(in1 + r1 * gn1);
    float h0 = (1.0f - z0)*n0 + z0*hpv.x;
    float h1 = (1.0f - z1)*n1 + z1*hpv.y;

    size_t base = ((size_t)(s*TSTEP + t)*BB + b);
    *(float2*)(d_hs1 + base*HH + i) = make_float2(h0, h1);
    d_hs1p[base*KP + kc] = packpair(h0, h1);
}

// ---------------- per-sentence carry (fp32 + packed) ----------------------------
__global__ void k_carry(const int* __restrict__ lens, int s)
{
    int e = blockIdx.x * blockDim.x + threadIdx.x;
    if (e >= BB*HH/2) return;
    int b  = e >> 9;
    int kc = e & 511;
    int i  = kc * 2;
    int idx = lens[s*BB + b] - 2;
    if (idx < 0) idx = 0;
    if (idx > TSTEP - 1) idx = TSTEP - 1;
    size_t base = ((size_t)(s*TSTEP + idx)*BB + b);
    *(float2*)(d_hc0 + (size_t)b*HH + i) = *(const float2*)(d_hs0 + base*HH + i);
    *(float2*)(d_hc1 + (size_t)b*HH + i) = *(const float2*)(d_hs1 + base*HH + i);
    d_hc0p[(size_t)b*KP + kc] = d_hs0p[base*KP + kc];
    d_hc1p[(size_t)b*KP + kc] = d_hs1p[base*KP + kc];
}

// ---------------- launcher ------------------------------------------------------
extern "C" void kernel_launch(void* const* d_in, const int* in_sizes, int n_in,
                              void* d_out, int out_size)
{
    (void)in_sizes; (void)n_in; (void)out_size;
    const int*   ids    = (const int*)  d_in[0];
    const int*   lens   = (const int*)  d_in[1];
    const float* embed  = (const float*)d_in[2];
    const float* W_ih0  = (const float*)d_in[3];
    const float* W_hh0  = (const float*)d_in[4];
    const float* b_ih0  = (const float*)d_in[5];
    const float* b_hh0  = (const float*)d_in[6];
    const float* W_ih1  = (const float*)d_in[7];
    const float* W_hh1  = (const float*)d_in[8];
    const float* b_ih1  = (const float*)d_in[9];
    const float* b_hh1  = (const float*)d_in[10];
    const float* W_out  = (const float*)d_in[11];
    float*       out    = (float*)d_out;

    uint2* wp0;  cudaGetSymbolAddress((void**)&wp0,  d_Wp0);
    uint2* wp1i; cudaGetSymbolAddress((void**)&wp1i, d_Wp1i);
    uint2* wp1h; cudaGetSymbolAddress((void**)&wp1h, d_Wp1h);
    uint2* wpo;  cudaGetSymbolAddress((void**)&wpo,  d_WpO);

    // reset carry state
    k_zero_carry<<<(BB*HH/2 + 255)/256, 256>>>();

    // gather embeddings
    k_gather<<<(NROWS*(EE/4) + 255)/256, 256>>>(ids, embed);

    // pack weights into split-bf16 hi/lo pairs
    k_packw<<<(GG*KP + 255)/256, 256>>>(W_hh0, wp0,  GG*KP);
    k_packw<<<(GG*KP + 255)/256, 256>>>(W_ih1, wp1i, GG*KP);
    k_packw<<<(GG*KP + 255)/256, 256>>>(W_hh1, wp1h, GG*KP);
    k_packw<<<(VV*KP + 255)/256, 256>>>(W_out, wpo,  VV*KP);

    // precompute layer-0 input gates: gi0 = x_all @ W_ih0^T + b_ih0 (fp32, K=512)
    k_sgemm<<<dim3(GG/128, NROWS/128), 256>>>(W_ih0, b_ih0, GG, EE);

    // sequential recurrence (tensor-core step GEMMs)
    for (int s = 0; s < SS; s++) {
        for (int t = 0; t < TSTEP; t++) {
            k_mma_step<<<dim3(GG/64, KSPL, 1), 128>>>(wp0, nullptr, 0, s, t);
            k_gru0<<<(BB*HH/2)/256, 256>>>(b_hh0, s, t);
            k_mma_step<<<dim3(GG/64, KSPL, 2), 128>>>(wp1i, wp1h, 1, s, t);
            k_gru1<<<(BB*HH/2)/256, 256>>>(b_ih1, b_hh1, s, t);
        }
        k_carry<<<(BB*HH/2)/256, 256>>>(lens, s);
    }

    // logits = hs1 @ W_out^T (tensor cores), remapped to (s, b, t, v)
    k_mma_logits<<<dim3(NROWS/128, VV/128), 256>>>(out);
}